// round 12
// baseline (speedup 1.0000x reference)
#include <cuda_runtime.h>

// glb_reduced_6d: [BT, 10, 6] float (d_in[0]) -> 60 floats/item
// orientation_6d: [BT, 6, 6]  float (d_in[1]) -> 36 floats/item
// out:            [BT, 24, 3] float           -> 72 floats/item
//
// Block = 128 threads / 64 items. Warp w: role = w&1, item = (w>>1)*32 + lane.
// Role 0: joints {0,3,6,9,12,13,14,15} (+zeros 7,8,10,11);
// Role 1: joints {1,2,4,5,16,17,18,19} (+zeros 20..23).
// Slot stride 98 floats: 8B-aligned slots, even offsets -> LDS.64, conflict-free.
// FULL template path: block known full (BT divisible by 64) -> no predicates.

#define STRIDE 98
#define ITEMS_PER_BLOCK 64
#define THREADS 128

__device__ __forceinline__ float fast_atan2p(float n, float w) {
    // atan2(n, w) with n >= 0; result in [0, pi]. ~1e-5 rad accuracy.
    float aw = fabsf(w);
    bool sw = n > aw;
    float num = sw ? aw : n;
    float den = sw ? n : aw;
    float r = __fdividef(num, den);
    float x2 = r * r;
    float p = -0.0117212f;
    p = fmaf(p, x2, 0.05265332f);
    p = fmaf(p, x2, -0.11643287f);
    p = fmaf(p, x2, 0.19354346f);
    p = fmaf(p, x2, -0.33262347f);
    p = fmaf(p, x2, 0.99997726f);
    float a = r * p;
    if (sw) a = 1.57079632679f - a;
    if (w < 0.f) a = 3.14159265359f - a;
    return a;
}

// d must be 8-byte aligned (even float offset in an 8B-aligned slot)
__device__ __forceinline__ void gs6(const float* d, float* __restrict__ m) {
    const float2* q = (const float2*)d;
    float2 q0 = q[0], q1 = q[1], q2 = q[2];
    float x = q0.x, y = q0.y, z = q1.x;
    float u = q1.y, v = q2.x, w = q2.y;
    float inv = rsqrtf(x * x + y * y + z * z);
    float b1x = x * inv, b1y = y * inv, b1z = z * inv;
    float dot = b1x * u + b1y * v + b1z * w;
    float c2x = u - dot * b1x, c2y = v - dot * b1y, c2z = w - dot * b1z;
    float inv2 = rsqrtf(c2x * c2x + c2y * c2y + c2z * c2z);
    float b2x = c2x * inv2, b2y = c2y * inv2, b2z = c2z * inv2;
    m[0] = b1x; m[1] = b1y; m[2] = b1z;
    m[3] = b2x; m[4] = b2y; m[5] = b2z;
    m[6] = b1y * b2z - b1z * b2y;
    m[7] = b1z * b2x - b1x * b2z;
    m[8] = b1x * b2y - b1y * b2x;
}

__device__ __forceinline__ void mmTN(const float* __restrict__ A, const float* __restrict__ B,
                                     float* __restrict__ C) {
    #pragma unroll
    for (int r = 0; r < 3; r++)
        #pragma unroll
        for (int c = 0; c < 3; c++)
            C[r * 3 + c] = A[0 * 3 + r] * B[0 * 3 + c]
                         + A[1 * 3 + r] * B[1 * 3 + c]
                         + A[2 * 3 + r] * B[2 * 3 + c];
}

__device__ __forceinline__ void m2aa(const float* __restrict__ m, float* __restrict__ ob) {
    float m00 = m[0], m01 = m[1], m02 = m[2];
    float m10 = m[3], m11 = m[4], m12 = m[5];
    float m20 = m[6], m21 = m[7], m22 = m[8];
    float t0 = fmaxf(1.f + m00 + m11 + m22, 0.f);
    float t1 = fmaxf(1.f + m00 - m11 - m22, 0.f);
    float t2 = fmaxf(1.f - m00 + m11 - m22, 0.f);
    float t3 = fmaxf(1.f - m00 - m11 + m22, 0.f);
    // Branchless 2-level argmax tournament; strict > preserves argmax
    // first-max-on-tie semantics.
    bool a01 = t1 > t0;
    bool a23 = t3 > t2;
    float ta = a01 ? t1 : t0;
    float tc = a23 ? t3 : t2;
    bool ab  = tc > ta;
    float qw = ab ? (a23 ? m10 - m01 : m02 - m20) : (a01 ? m21 - m12 : t0);
    float qx = ab ? (a23 ? m20 + m02 : m10 + m01) : (a01 ? t1        : m21 - m12);
    float qy = ab ? (a23 ? m21 + m12 : t2       ) : (a01 ? m10 + m01 : m02 - m20);
    float qz = ab ? (a23 ? t3        : m12 + m21) : (a01 ? m02 + m20 : m10 - m01);
    // 1/(2*max(qa,0.1)) cancels (unit quat: sin(half)=|vec|):
    // out = vec_raw * (2*atan2(|vec_raw|, qw_raw) / |vec_raw|)
    float s = qx * qx + qy * qy + qz * qz;
    s = fmaxf(s, 1e-24f);
    float inv_n = rsqrtf(s);
    float n = s * inv_n;
    float half = fast_atan2p(n, qw);
    float factor = 2.f * half * inv_n;
    ob[0] = qx * factor; ob[1] = qy * factor; ob[2] = qz * factor;
}

__device__ __forceinline__ void sts2(float* p, float a, float b) {
    *(float2*)p = make_float2(a, b);
}

template <bool FULL>
__device__ __forceinline__ void do_block(
    const float* __restrict__ glb, const float* __restrict__ ori,
    float* __restrict__ out, float* __restrict__ sm, int base, int cnt)
{
    const int tid = threadIdx.x;
    const int warp = tid >> 5;
    const int lane = tid & 31;

    // ---- Stage glb: 64 items x 15 f4, coalesced; slot floats [0..59] ----
    // Incremental div/mod: j = k*128 + tid; 128 = 8*15 + 8.
    {
        const float4* src = (const float4*)(glb + (size_t)base * 60);
        int ntot = FULL ? ITEMS_PER_BLOCK * 15 : cnt * 15;
        int r = tid % 15;
        int addr = (tid / 15) * STRIDE + r * 4;
        #pragma unroll
        for (int k = 0; k < 8; k++) {
            int j = k * THREADS + tid;
            if (j < ntot) {
                float4 v = src[j];
                float2* p = (float2*)(sm + addr);
                p[0] = make_float2(v.x, v.y);
                p[1] = make_float2(v.z, v.w);
            }
            r += 8; addr += 8 * STRIDE + 32;
            if (r >= 15) { r -= 15; addr += STRIDE - 60; }
        }
    }
    // ---- Stage ori: 64 items x 9 f4; slot floats [60..95]; 128 = 14*9 + 2 ----
    {
        const float4* src = (const float4*)(ori + (size_t)base * 36);
        int ntot = FULL ? ITEMS_PER_BLOCK * 9 : cnt * 9;
        int r = tid % 9;
        int addr = (tid / 9) * STRIDE + 60 + r * 4;
        #pragma unroll
        for (int k = 0; k < 5; k++) {
            int j = k * THREADS + tid;
            if (j < ntot) {
                float4 v = src[j];
                float2* p = (float2*)(sm + addr);
                p[0] = make_float2(v.x, v.y);
                p[1] = make_float2(v.z, v.w);
            }
            r += 2; addr += 14 * STRIDE + 8;
            if (r >= 9) { r -= 9; addr += STRIDE - 36; }
        }
    }
    __syncthreads();

    const int role = warp & 1;
    const int item_local = (warp >> 1) * 32 + lane;
    float* my = sm + item_local * STRIDE;
    const bool valid = FULL || (item_local < cnt);

    // ---- Compute phase: smem READ-ONLY; results in registers ----
    float res[24];
    if (valid) {
        float A[9], B9[9], C9[9], D9[9], L[9];
        if (role == 0) {
            gs6(my + 60, A);  m2aa(A, res + 0);      // joint 0 (root)
            gs6(my + 12, A);  m2aa(A, res + 3);      // joint 3 (Y3, kept)
            gs6(my + 18, B9);                        // Y6
            mmTN(A, B9, L);   m2aa(L, res + 6);      // joint 6  = Y3^T Y6
            gs6(my + 24, C9);                        // Y9
            mmTN(B9, C9, L);  m2aa(L, res + 9);      // joint 9  = Y6^T Y9
            gs6(my + 30, D9);                        // Y12 (kept)
            mmTN(C9, D9, L);  m2aa(L, res + 12);     // joint 12 = Y9^T Y12
            gs6(my + 36, A);                         // Y13
            mmTN(C9, A, L);   m2aa(L, res + 15);     // joint 13 = Y9^T Y13
            gs6(my + 42, A);                         // Y14
            mmTN(C9, A, L);   m2aa(L, res + 18);     // joint 14 = Y9^T Y14
            gs6(my + 78, A);                         // O3
            mmTN(D9, A, L);   m2aa(L, res + 21);     // joint 15 = Y12^T O3
        } else {
            gs6(my + 0,  A);  m2aa(A, res + 0);      // joint 1 (Y1)
            gs6(my + 66, B9);                        // O1
            mmTN(A, B9, L);   m2aa(L, res + 3);      // joint 4  = Y1^T O1
            gs6(my + 6,  A);  m2aa(A, res + 6);      // joint 2 (Y2)
            gs6(my + 72, B9);                        // O2
            mmTN(A, B9, L);   m2aa(L, res + 9);      // joint 5  = Y2^T O2
            gs6(my + 36, A);  gs6(my + 48, B9);      // Y13, Y16 (kept)
            mmTN(A, B9, L);   m2aa(L, res + 12);     // joint 16 = Y13^T Y16
            gs6(my + 42, A);  gs6(my + 54, C9);      // Y14, Y17 (kept)
            mmTN(A, C9, L);   m2aa(L, res + 15);     // joint 17 = Y14^T Y17
            gs6(my + 84, A);                         // O4
            mmTN(B9, A, L);   m2aa(L, res + 18);     // joint 18 = Y16^T O4
            gs6(my + 90, A);                         // O5
            mmTN(C9, A, L);   m2aa(L, res + 21);     // joint 19 = Y17^T O5
        }
    }
    __syncthreads();   // all input reads complete

    // ---- Store phase: disjoint smem writes per role, float2-vectorized ----
    // (slot base is 8B-aligned; all f2 stores are at even float offsets)
    if (valid) {
        if (role == 0) {
            // owned runs: [0..2], [9..11], [18..47]
            sts2(my + 0,  res[0],  res[1]);  my[2]  = res[2];    // joint 0
            my[9] = res[3];  sts2(my + 10, res[4], res[5]);      // joint 3
            sts2(my + 18, res[6],  res[7]);                      // joint 6 xy
            sts2(my + 20, res[8],  0.f);                         // joint 6 z | j7
            sts2(my + 22, 0.f, 0.f);                             // j7
            sts2(my + 24, 0.f, 0.f);                             // j8
            sts2(my + 26, 0.f, res[9]);                          // j8 | joint 9 x
            sts2(my + 28, res[10], res[11]);                     // joint 9 yz
            sts2(my + 30, 0.f, 0.f);                             // j10
            sts2(my + 32, 0.f, 0.f);                             // j10|j11
            sts2(my + 34, 0.f, 0.f);                             // j11
            sts2(my + 36, res[12], res[13]);                     // joint 12
            sts2(my + 38, res[14], res[15]);                     // j12 | j13
            sts2(my + 40, res[16], res[17]);                     // joint 13
            sts2(my + 42, res[18], res[19]);                     // joint 14
            sts2(my + 44, res[20], res[21]);                     // j14 | j15
            sts2(my + 46, res[22], res[23]);                     // joint 15
        } else {
            // owned runs: [3..8], [12..17], [48..71]
            my[3] = res[0];  sts2(my + 4, res[1], res[2]);       // joint 1
            sts2(my + 6, res[6], res[7]);  my[8] = res[8];       // joint 2
            sts2(my + 12, res[3],  res[4]);                      // joint 4 xy
            sts2(my + 14, res[5],  res[9]);                      // j4 z | j5 x
            sts2(my + 16, res[10], res[11]);                     // joint 5 yz
            sts2(my + 48, res[12], res[13]);                     // joint 16
            sts2(my + 50, res[14], res[15]);                     // j16 | j17
            sts2(my + 52, res[16], res[17]);                     // joint 17
            sts2(my + 54, res[18], res[19]);                     // joint 18
            sts2(my + 56, res[20], res[21]);                     // j18 | j19
            sts2(my + 58, res[22], res[23]);                     // joint 19
            #pragma unroll
            for (int k = 60; k < 72; k += 2) sts2(my + k, 0.f, 0.f); // j20..23
        }
    }
    __syncthreads();

    // ---- Coalesced f4 stores; incremental addressing (128 = 7*18 + 2) ----
    {
        float4* dst = (float4*)(out + (size_t)base * 72);
        int ntot = FULL ? ITEMS_PER_BLOCK * 18 : cnt * 18;
        int r = tid % 18;
        int addr = (tid / 18) * STRIDE + r * 4;
        #pragma unroll
        for (int k = 0; k < 9; k++) {
            int j = k * THREADS + tid;
            if (j < ntot) {
                const float2* p = (const float2*)(sm + addr);
                float2 a = p[0], b = p[1];
                dst[j] = make_float4(a.x, a.y, b.x, b.y);
            }
            r += 2; addr += 7 * STRIDE + 8;
            if (r >= 18) { r -= 18; addr += STRIDE - 72; }
        }
    }
}

__global__ void __launch_bounds__(THREADS, 5)
pose_kernel(const float* __restrict__ glb, const float* __restrict__ ori,
            float* __restrict__ out, int n_items)
{
    __shared__ float sm[ITEMS_PER_BLOCK * STRIDE];
    const int base = blockIdx.x * ITEMS_PER_BLOCK;
    int cnt = n_items - base;
    if (cnt > ITEMS_PER_BLOCK) cnt = ITEMS_PER_BLOCK;
    if (cnt < 0) cnt = 0;

    if (cnt == ITEMS_PER_BLOCK) {
        do_block<true>(glb, ori, out, sm, base, cnt);   // hot path (BT % 64 == 0)
    } else {
        do_block<false>(glb, ori, out, sm, base, cnt);  // generic tail path
    }
}

extern "C" void kernel_launch(void* const* d_in, const int* in_sizes, int n_in,
                              void* d_out, int out_size) {
    const float* glb = (const float*)d_in[0];   // [BT,10,6]
    const float* ori = (const float*)d_in[1];   // [BT,6,6]
    float* out = (float*)d_out;                 // [BT,24,3]
    int n_items = in_sizes[0] / 60;
    int blocks = (n_items + ITEMS_PER_BLOCK - 1) / ITEMS_PER_BLOCK;
    pose_kernel<<<blocks, THREADS>>>(glb, ori, out, n_items);
}